// round 5
// baseline (speedup 1.0000x reference)
#include <cuda_runtime.h>
#include <cuda_fp16.h>
#include <cstdint>

#define NT 256

// ---------------- device scratch (no runtime allocation) ----------------
__device__ float  g_A [1600 * 512];       // enc_proj + b1   [bt][inner]
__device__ float  g_Dp[ 256 * 512];       // dec_proj        [b*64+u][inner]
__device__ __half g_w1[2 * 512 * 320];    // fp16 W1 halves  [which][inner][e]
__device__ __half g_w2[1024 * 512];       // fp16 W2         [v][k]

// ---------------- baseline-ISA helpers (no sm_103a features) ----------------
__device__ __forceinline__ uint32_t smem_u32(const void* p) {
    uint32_t a;
    asm("{ .reg .u64 t; cvta.to.shared.u64 t, %1; cvt.u32.u64 %0, t; }" : "=r"(a) : "l"(p));
    return a;
}
__device__ __forceinline__ void cp16(uint32_t d, const void* s) {
    asm volatile("cp.async.cg.shared.global [%0], [%1], 16;" :: "r"(d), "l"(s));
}
__device__ __forceinline__ void cp_commit() { asm volatile("cp.async.commit_group;" ::: "memory"); }
template <int N> __device__ __forceinline__ void cp_wait() {
    asm volatile("cp.async.wait_group %0;" :: "n"(N) : "memory");
}
__device__ __forceinline__ void ldsm4(uint32_t& r0, uint32_t& r1, uint32_t& r2, uint32_t& r3, uint32_t a) {
    asm volatile("ldmatrix.sync.aligned.m8n8.x4.shared.b16 {%0,%1,%2,%3}, [%4];"
                 : "=r"(r0), "=r"(r1), "=r"(r2), "=r"(r3) : "r"(a));
}
__device__ __forceinline__ void mma16816(float* d, uint32_t a0, uint32_t a1, uint32_t a2, uint32_t a3,
                                         uint32_t b0, uint32_t b1) {
    asm volatile(
        "mma.sync.aligned.m16n8k16.row.col.f32.f16.f16.f32 "
        "{%0,%1,%2,%3}, {%4,%5,%6,%7}, {%8,%9}, {%0,%1,%2,%3};"
        : "+f"(d[0]), "+f"(d[1]), "+f"(d[2]), "+f"(d[3])
        : "r"(a0), "r"(a1), "r"(a2), "r"(a3), "r"(b0), "r"(b1));
}
__device__ __forceinline__ uint32_t pack_h2(float a, float b) {
    __half2 h = __floats2half2_rn(a, b);
    return *reinterpret_cast<uint32_t*>(&h);
}
__device__ __forceinline__ float fast_tanh(float x) {
    x = fminf(fmaxf(x, -15.0f), 15.0f);
    float e;
    asm("ex2.approx.f32 %0, %1;" : "=f"(e) : "f"(x * 2.8853900817779268f));  // exp(2x)
    float r;
    asm("rcp.approx.f32 %0, %1;" : "=f"(r) : "f"(e + 1.0f));
    return (e - 1.0f) * r;
}

// ---------------- weight prep ----------------
__global__ void prep_w1(const float* __restrict__ W1) {
    int g = blockIdx.x * NT + threadIdx.x;          // < 40960 (2*512*320/8)
    int which = g / 20480;
    int rem = g % 20480;
    int i = rem / 40;                               // inner row
    int c8 = rem % 40;                              // 8-half chunk
    const float4* s = (const float4*)(W1 + (size_t)i * 640 + which * 320 + c8 * 8);
    float4 a = s[0], b = s[1];
    uint4 q;
    q.x = pack_h2(a.x, a.y); q.y = pack_h2(a.z, a.w);
    q.z = pack_h2(b.x, b.y); q.w = pack_h2(b.z, b.w);
    ((uint4*)g_w1)[g] = q;
}
__global__ void prep_w2(const float* __restrict__ W2) {
    int g = blockIdx.x * NT + threadIdx.x;          // < 65536 (1024*512/8)
    const float4* s = (const float4*)(W2 + (size_t)g * 8);
    float4 a = s[0], b = s[1];
    uint4 q;
    q.x = pack_h2(a.x, a.y); q.y = pack_h2(a.z, a.w);
    q.z = pack_h2(b.x, b.y); q.w = pack_h2(b.z, b.w);
    ((uint4*)g_w2)[g] = q;
}

// ---------------- proj kernel: enc/dec @ W1-half, mma.sync ----------------
// A smem: 128 rows x 320 halfs, row stride 640B (=5*128B), XOR-8 swizzle -> conflict-free ldmatrix
// B smem: 2 x (128n x 32k) fp16, row stride 64B, XOR-4 swizzle
#define PJ_A 0
#define PJ_B 81920
#define PJ_SMEM (81920 + 2 * 8192)

__global__ __launch_bounds__(NT, 1) void proj_kernel(const float* __restrict__ enc,
                                                     const float* __restrict__ dec,
                                                     const float* __restrict__ b1) {
    extern __shared__ char sm[];
    uint32_t smb = smem_u32(sm);
    int tid = threadIdx.x, lane = tid & 31, wid = tid >> 5;
    bool isenc = blockIdx.x < 13;
    int mt = isenc ? (int)blockIdx.x : (int)blockIdx.x - 13;
    int Mtot = isenc ? 1600 : 256;
    const float* src = isenc ? enc : dec;
    const __half* Bsrc = g_w1 + (isenc ? 0 : 1) * (512 * 320);

    // prologue: A fp32 -> fp16 swizzled smem (zero-fill invalid rows)
    {
        int r = tid >> 1, hf = tid & 1;
        int m = mt * 128 + r;
        bool valid = m < Mtot;
        const float4* pa = (const float4*)(src + (size_t)m * 320 + hf * 160);
#pragma unroll 4
        for (int c2 = 0; c2 < 20; ++c2) {
            float4 a = valid ? pa[2 * c2] : make_float4(0.f, 0.f, 0.f, 0.f);
            float4 b = valid ? pa[2 * c2 + 1] : make_float4(0.f, 0.f, 0.f, 0.f);
            uint4 q;
            q.x = pack_h2(a.x, a.y); q.y = pack_h2(a.z, a.w);
            q.z = pack_h2(b.x, b.y); q.w = pack_h2(b.z, b.w);
            int cg = hf * 20 + c2;
            *(uint4*)(sm + PJ_A + r * 640 + ((cg ^ (r & 7)) << 4)) = q;
        }
    }
    __syncthreads();

    int wm = wid & 1, wn = wid >> 1;                 // 2 x 4 warps, warp tile 64x32
    uint32_t aBase = smb + PJ_A + (wm * 64 + (lane & 15)) * 640;
    uint32_t bRowBase = smb + PJ_B + (wn * 32 + (lane & 15)) * 64;
    int ln7 = lane & 7, ln3 = lane & 3, lnHi = lane >> 4;

    for (int nt = 0; nt < 4; ++nt) {
        float acc[4][4][4];
#pragma unroll
        for (int i = 0; i < 4; ++i)
#pragma unroll
            for (int j = 0; j < 4; ++j)
#pragma unroll
                for (int q = 0; q < 4; ++q) acc[i][j][q] = 0.f;

        // B chunk loader: thread -> (n = tid>>1, 2 chunks)
        {
            int n = tid >> 1, cp = tid & 1;
            const __half* s = Bsrc + (size_t)(nt * 128 + n) * 320 + cp * 16;
            uint32_t d0 = smb + PJ_B + n * 64;
#pragma unroll
            for (int c = 0; c < 2; ++c) {
                int cc = cp * 2 + c;
                cp16(d0 + ((cc ^ (n & 3)) << 4), s + c * 8);
            }
            cp_commit();
        }
        for (int kc = 0; kc < 10; ++kc) {
            if (kc < 9) {
                int buf = (kc + 1) & 1;
                int n = tid >> 1, cp = tid & 1;
                const __half* s = Bsrc + (size_t)(nt * 128 + n) * 320 + (kc + 1) * 32 + cp * 16;
                uint32_t d0 = smb + PJ_B + buf * 8192 + n * 64;
#pragma unroll
                for (int c = 0; c < 2; ++c) {
                    int cc = cp * 2 + c;
                    cp16(d0 + ((cc ^ (n & 3)) << 4), s + c * 8);
                }
                cp_commit();
                cp_wait<1>();
            } else {
                cp_wait<0>();
            }
            __syncthreads();
            uint32_t bBuf = bRowBase + (kc & 1) * 8192;
#pragma unroll
            for (int k16 = 0; k16 < 2; ++k16) {
                uint32_t ach = (uint32_t)(kc * 4 + k16 * 2 + lnHi);
                uint32_t a[4][4];
#pragma unroll
                for (int mf = 0; mf < 4; ++mf)
                    ldsm4(a[mf][0], a[mf][1], a[mf][2], a[mf][3],
                          aBase + mf * (16 * 640) + ((ach ^ ln7) << 4));
                uint32_t bq[2][4];
#pragma unroll
                for (int np = 0; np < 2; ++np)
                    ldsm4(bq[np][0], bq[np][1], bq[np][2], bq[np][3],
                          bBuf + np * (16 * 64) + ((((uint32_t)(k16 * 2 + lnHi)) ^ ln3) << 4));
#pragma unroll
                for (int mf = 0; mf < 4; ++mf)
#pragma unroll
                    for (int nf = 0; nf < 4; ++nf) {
                        int np = nf >> 1, hi = nf & 1;
                        mma16816(acc[mf][nf], a[mf][0], a[mf][1], a[mf][2], a[mf][3],
                                 bq[np][hi], bq[np][hi + 2]);
                    }
            }
            __syncthreads();
        }
        // epilogue: write fp32 proj (+b1 for enc)
        int colb = nt * 128 + wn * 32;
        float* dstb = isenc ? g_A : g_Dp;
#pragma unroll
        for (int mf = 0; mf < 4; ++mf) {
            int m = mt * 128 + wm * 64 + mf * 16 + (lane >> 2);
#pragma unroll
            for (int nf = 0; nf < 4; ++nf) {
                int col = colb + nf * 8 + (lane & 3) * 2;
                float bx = 0.f, by = 0.f;
                if (isenc) { float2 bv = *(const float2*)(b1 + col); bx = bv.x; by = bv.y; }
                if (m < Mtot) {
                    float2 o = { acc[mf][nf][0] + bx, acc[mf][nf][1] + by };
                    *(float2*)(dstb + (size_t)m * 512 + col) = o;
                }
                if (m + 8 < Mtot) {
                    float2 o = { acc[mf][nf][2] + bx, acc[mf][nf][3] + by };
                    *(float2*)(dstb + (size_t)(m + 8) * 512 + col) = o;
                }
            }
        }
        __syncthreads();
    }
}

// ---------------- main kernel: out = tanh(encp+decp) @ W2^T + b2 ----------------
// A smem: 128 rows x 512 halfs (1024B rows, XOR-8 swizzle) = 128KB, built once per CTA
// B smem: 2 x (256n x 32k) fp16 (64B rows, XOR-4 swizzle) = 32KB
#define MA_A 0
#define MA_B 131072
#define MA_SMEM (131072 + 2 * 16384)

__global__ __launch_bounds__(NT, 1) void main_kernel(const float* __restrict__ b2,
                                                     float* __restrict__ out) {
    extern __shared__ char sm[];
    uint32_t smb = smem_u32(sm);
    int tid = threadIdx.x, lane = tid & 31, wid = tid >> 5;
    int m0 = blockIdx.x * 128;

    // prologue: h = fp16(tanh(enc_proj + dec_proj)) into swizzled smem
    {
        int r = tid >> 1, hf = tid & 1;
        int m = m0 + r;
        const float4* pa = (const float4*)(g_A + (size_t)(m >> 6) * 512 + hf * 256);
        int b = m / 25600, u = m & 63;
        const float4* pd = (const float4*)(g_Dp + (size_t)(b * 64 + u) * 512 + hf * 256);
#pragma unroll 4
        for (int c2 = 0; c2 < 32; ++c2) {
            float4 x0 = pa[2 * c2], x1 = pa[2 * c2 + 1];
            float4 y0 = pd[2 * c2], y1 = pd[2 * c2 + 1];
            uint4 q;
            q.x = pack_h2(fast_tanh(x0.x + y0.x), fast_tanh(x0.y + y0.y));
            q.y = pack_h2(fast_tanh(x0.z + y0.z), fast_tanh(x0.w + y0.w));
            q.z = pack_h2(fast_tanh(x1.x + y1.x), fast_tanh(x1.y + y1.y));
            q.w = pack_h2(fast_tanh(x1.z + y1.z), fast_tanh(x1.w + y1.w));
            int cg = hf * 32 + c2;
            *(uint4*)(sm + MA_A + r * 1024 + ((cg ^ (r & 7)) << 4)) = q;
        }
    }
    __syncthreads();

    int wm = wid & 1, wn = wid >> 1;                 // 2 x 4 warps, warp tile 64x64
    uint32_t aBase = smb + MA_A + (wm * 64 + (lane & 15)) * 1024;
    uint32_t bRowBase = smb + MA_B + (wn * 64 + (lane & 15)) * 64;
    int ln7 = lane & 7, ln3 = lane & 3, lnHi = lane >> 4;

    for (int nt = 0; nt < 4; ++nt) {
        const __half* Bsrc = g_w2 + (size_t)(nt * 256) * 512;
        float acc[4][8][4];
#pragma unroll
        for (int i = 0; i < 4; ++i)
#pragma unroll
            for (int j = 0; j < 8; ++j)
#pragma unroll
                for (int q = 0; q < 4; ++q) acc[i][j][q] = 0.f;

        {   // B chunk 0: one full 64B row per thread
            int n = tid;
            const __half* s = Bsrc + (size_t)n * 512;
            uint32_t d0 = smb + MA_B + n * 64;
#pragma unroll
            for (int c = 0; c < 4; ++c) cp16(d0 + ((c ^ (n & 3)) << 4), s + c * 8);
            cp_commit();
        }
        for (int kc = 0; kc < 16; ++kc) {
            if (kc < 15) {
                int buf = (kc + 1) & 1;
                int n = tid;
                const __half* s = Bsrc + (size_t)n * 512 + (kc + 1) * 32;
                uint32_t d0 = smb + MA_B + buf * 16384 + n * 64;
#pragma unroll
                for (int c = 0; c < 4; ++c) cp16(d0 + ((c ^ (n & 3)) << 4), s + c * 8);
                cp_commit();
                cp_wait<1>();
            } else {
                cp_wait<0>();
            }
            __syncthreads();
            uint32_t bBuf = bRowBase + (kc & 1) * 16384;
#pragma unroll
            for (int k16 = 0; k16 < 2; ++k16) {
                uint32_t ach = (uint32_t)(kc * 4 + k16 * 2 + lnHi);
                uint32_t a[4][4];
#pragma unroll
                for (int mf = 0; mf < 4; ++mf)
                    ldsm4(a[mf][0], a[mf][1], a[mf][2], a[mf][3],
                          aBase + mf * 16384 + ((ach ^ ln7) << 4));
                uint32_t bq[4][4];
#pragma unroll
                for (int np = 0; np < 4; ++np)
                    ldsm4(bq[np][0], bq[np][1], bq[np][2], bq[np][3],
                          bBuf + np * (16 * 64) + ((((uint32_t)(k16 * 2 + lnHi)) ^ ln3) << 4));
#pragma unroll
                for (int mf = 0; mf < 4; ++mf)
#pragma unroll
                    for (int nf = 0; nf < 8; ++nf) {
                        int np = nf >> 1, hi = nf & 1;
                        mma16816(acc[mf][nf], a[mf][0], a[mf][1], a[mf][2], a[mf][3],
                                 bq[np][hi], bq[np][hi + 2]);
                    }
            }
            __syncthreads();
        }
        // epilogue: +b2, fp32 store
        int colb = nt * 256 + wn * 64;
#pragma unroll
        for (int mf = 0; mf < 4; ++mf) {
            int row = m0 + wm * 64 + mf * 16 + (lane >> 2);
#pragma unroll
            for (int nf = 0; nf < 8; ++nf) {
                int col = colb + nf * 8 + (lane & 3) * 2;
                float2 bv = *(const float2*)(b2 + col);
                float2 o0 = { acc[mf][nf][0] + bv.x, acc[mf][nf][1] + bv.y };
                float2 o1 = { acc[mf][nf][2] + bv.x, acc[mf][nf][3] + bv.y };
                *(float2*)(out + (size_t)row * 1024 + col) = o0;
                *(float2*)(out + (size_t)(row + 8) * 1024 + col) = o1;
            }
        }
    }
}

// ---------------- launch ----------------
extern "C" void kernel_launch(void* const* d_in, const int* in_sizes, int n_in,
                              void* d_out, int out_size) {
    (void)in_sizes; (void)n_in; (void)out_size;
    const float* enc = (const float*)d_in[0];
    const float* dec = (const float*)d_in[1];
    const float* W1  = (const float*)d_in[2];
    const float* b1  = (const float*)d_in[3];
    const float* W2  = (const float*)d_in[4];
    const float* b2  = (const float*)d_in[5];
    float* out = (float*)d_out;

    cudaFuncSetAttribute(proj_kernel, cudaFuncAttributeMaxDynamicSharedMemorySize, PJ_SMEM);
    cudaFuncSetAttribute(main_kernel, cudaFuncAttributeMaxDynamicSharedMemorySize, MA_SMEM);

    prep_w1<<<160, NT>>>(W1);
    prep_w2<<<256, NT>>>(W2);
    proj_kernel<<<15, NT, PJ_SMEM>>>(enc, dec, b1);
    main_kernel<<<800, NT, MA_SMEM>>>(b2, out);
}

// round 7
// speedup vs baseline: 1.3387x; 1.3387x over previous
#include <cuda_runtime.h>
#include <cuda_fp16.h>
#include <cstdint>

#define NT 256

// ---------------- device scratch (no runtime allocation) ----------------
__device__ float  g_A [1600 * 512];       // enc_proj + b1   [bt][inner]
__device__ float  g_Dp[ 256 * 512];       // dec_proj        [b*64+u][inner]
__device__ __half g_w1[2 * 512 * 320];    // fp16 W1 halves  [which][inner][e]
__device__ __half g_w2[1024 * 512];       // fp16 W2, TILE-LINEAR ldsm order [ci=nt*16+kc][ng][k16][32x16B]

// ---------------- baseline-ISA helpers (no sm_103a features) ----------------
__device__ __forceinline__ uint32_t smem_u32(const void* p) {
    uint32_t a;
    asm("{ .reg .u64 t; cvta.to.shared.u64 t, %1; cvt.u32.u64 %0, t; }" : "=r"(a) : "l"(p));
    return a;
}
__device__ __forceinline__ void cp16(uint32_t d, const void* s) {
    asm volatile("cp.async.cg.shared.global [%0], [%1], 16;" :: "r"(d), "l"(s));
}
__device__ __forceinline__ void cp_commit() { asm volatile("cp.async.commit_group;" ::: "memory"); }
template <int N> __device__ __forceinline__ void cp_wait() {
    asm volatile("cp.async.wait_group %0;" :: "n"(N) : "memory");
}
__device__ __forceinline__ void ldsm4(uint32_t& r0, uint32_t& r1, uint32_t& r2, uint32_t& r3, uint32_t a) {
    asm volatile("ldmatrix.sync.aligned.m8n8.x4.shared.b16 {%0,%1,%2,%3}, [%4];"
                 : "=r"(r0), "=r"(r1), "=r"(r2), "=r"(r3) : "r"(a));
}
__device__ __forceinline__ void mma16816(float* d, uint32_t a0, uint32_t a1, uint32_t a2, uint32_t a3,
                                         uint32_t b0, uint32_t b1) {
    asm volatile(
        "mma.sync.aligned.m16n8k16.row.col.f32.f16.f16.f32 "
        "{%0,%1,%2,%3}, {%4,%5,%6,%7}, {%8,%9}, {%0,%1,%2,%3};"
        : "+f"(d[0]), "+f"(d[1]), "+f"(d[2]), "+f"(d[3])
        : "r"(a0), "r"(a1), "r"(a2), "r"(a3), "r"(b0), "r"(b1));
}
__device__ __forceinline__ uint32_t pack_h2(float a, float b) {
    __half2 h = __floats2half2_rn(a, b);
    return *reinterpret_cast<uint32_t*>(&h);
}
__device__ __forceinline__ float fast_tanh(float x) {
    x = fminf(fmaxf(x, -15.0f), 15.0f);
    float e;
    asm("ex2.approx.f32 %0, %1;" : "=f"(e) : "f"(x * 2.8853900817779268f));  // exp(2x)
    float r;
    asm("rcp.approx.f32 %0, %1;" : "=f"(r) : "f"(e + 1.0f));
    return (e - 1.0f) * r;
}

// ---------------- weight prep ----------------
__global__ void prep_w1(const float* __restrict__ W1) {
    int g = blockIdx.x * NT + threadIdx.x;          // < 40960 (2*512*320/8)
    int which = g / 20480;
    int rem = g % 20480;
    int i = rem / 40;                               // inner row
    int c8 = rem % 40;                              // 8-half chunk
    const float4* s = (const float4*)(W1 + (size_t)i * 640 + which * 320 + c8 * 8);
    float4 a = s[0], b = s[1];
    uint4 q;
    q.x = pack_h2(a.x, a.y); q.y = pack_h2(a.z, a.w);
    q.z = pack_h2(b.x, b.y); q.w = pack_h2(b.z, b.w);
    ((uint4*)g_w1)[g] = q;
}
// Tile-linear W2, matching main kernel's read: unit o (16B):
//   o = ci*1024 + ng*64 + k16*32 + u,   blk = o>>5 = ci*32 + ng*2 + k16
//   k16 = blk&1, ng = (blk>>1)&15, kc = (blk>>5)&15, nt = blk>>9
//   u: matrix m = u>>3 (nsub=m&1, ksub=m>>1), row r = u&7
__global__ void prep_w2(const float* __restrict__ W2) {
    int o = blockIdx.x * NT + threadIdx.x;          // < 65536
    int u = o & 31, blk = o >> 5;
    int k16 = blk & 1, ng = (blk >> 1) & 15, kc = (blk >> 5) & 15, nt = blk >> 9;
    int m = u >> 3, r = u & 7;
    int v = nt * 256 + ng * 16 + (m & 1) * 8 + r;
    int k = kc * 32 + k16 * 16 + (m >> 1) * 8;
    const float4* s = (const float4*)(W2 + (size_t)v * 512 + k);
    float4 a = s[0], b = s[1];
    uint4 q;
    q.x = pack_h2(a.x, a.y); q.y = pack_h2(a.z, a.w);
    q.z = pack_h2(b.x, b.y); q.w = pack_h2(b.z, b.w);
    ((uint4*)g_w2)[o] = q;
}

// ---------------- proj kernel: enc/dec @ W1-half, mma.sync (unchanged, passing) ----------------
#define PJ_A 0
#define PJ_B 81920
#define PJ_SMEM (81920 + 2 * 8192)

__global__ __launch_bounds__(NT, 1) void proj_kernel(const float* __restrict__ enc,
                                                     const float* __restrict__ dec,
                                                     const float* __restrict__ b1) {
    extern __shared__ char sm[];
    uint32_t smb = smem_u32(sm);
    int tid = threadIdx.x, lane = tid & 31, wid = tid >> 5;
    bool isenc = blockIdx.x < 13;
    int mt = isenc ? (int)blockIdx.x : (int)blockIdx.x - 13;
    int Mtot = isenc ? 1600 : 256;
    const float* src = isenc ? enc : dec;
    const __half* Bsrc = g_w1 + (isenc ? 0 : 1) * (512 * 320);

    {
        int r = tid >> 1, hf = tid & 1;
        int m = mt * 128 + r;
        bool valid = m < Mtot;
        const float4* pa = (const float4*)(src + (size_t)m * 320 + hf * 160);
#pragma unroll 4
        for (int c2 = 0; c2 < 20; ++c2) {
            float4 a = valid ? pa[2 * c2] : make_float4(0.f, 0.f, 0.f, 0.f);
            float4 b = valid ? pa[2 * c2 + 1] : make_float4(0.f, 0.f, 0.f, 0.f);
            uint4 q;
            q.x = pack_h2(a.x, a.y); q.y = pack_h2(a.z, a.w);
            q.z = pack_h2(b.x, b.y); q.w = pack_h2(b.z, b.w);
            int cg = hf * 20 + c2;
            *(uint4*)(sm + PJ_A + r * 640 + ((cg ^ (r & 7)) << 4)) = q;
        }
    }
    __syncthreads();

    int wm = wid & 1, wn = wid >> 1;
    uint32_t aBase = smb + PJ_A + (wm * 64 + (lane & 15)) * 640;
    uint32_t bRowBase = smb + PJ_B + (wn * 32 + (lane & 15)) * 64;
    int ln7 = lane & 7, ln3 = lane & 3, lnHi = lane >> 4;

    for (int nt = 0; nt < 4; ++nt) {
        float acc[4][4][4];
#pragma unroll
        for (int i = 0; i < 4; ++i)
#pragma unroll
            for (int j = 0; j < 4; ++j)
#pragma unroll
                for (int q = 0; q < 4; ++q) acc[i][j][q] = 0.f;
        {
            int n = tid >> 1, cp = tid & 1;
            const __half* s = Bsrc + (size_t)(nt * 128 + n) * 320 + cp * 16;
            uint32_t d0 = smb + PJ_B + n * 64;
#pragma unroll
            for (int c = 0; c < 2; ++c) {
                int cc = cp * 2 + c;
                cp16(d0 + ((cc ^ (n & 3)) << 4), s + c * 8);
            }
            cp_commit();
        }
        for (int kc = 0; kc < 10; ++kc) {
            if (kc < 9) {
                int buf = (kc + 1) & 1;
                int n = tid >> 1, cp = tid & 1;
                const __half* s = Bsrc + (size_t)(nt * 128 + n) * 320 + (kc + 1) * 32 + cp * 16;
                uint32_t d0 = smb + PJ_B + buf * 8192 + n * 64;
#pragma unroll
                for (int c = 0; c < 2; ++c) {
                    int cc = cp * 2 + c;
                    cp16(d0 + ((cc ^ (n & 3)) << 4), s + c * 8);
                }
                cp_commit();
                cp_wait<1>();
            } else {
                cp_wait<0>();
            }
            __syncthreads();
            uint32_t bBuf = bRowBase + (kc & 1) * 8192;
#pragma unroll
            for (int k16 = 0; k16 < 2; ++k16) {
                uint32_t ach = (uint32_t)(kc * 4 + k16 * 2 + lnHi);
                uint32_t a[4][4];
#pragma unroll
                for (int mf = 0; mf < 4; ++mf)
                    ldsm4(a[mf][0], a[mf][1], a[mf][2], a[mf][3],
                          aBase + mf * (16 * 640) + ((ach ^ ln7) << 4));
                uint32_t bq[2][4];
#pragma unroll
                for (int np = 0; np < 2; ++np)
                    ldsm4(bq[np][0], bq[np][1], bq[np][2], bq[np][3],
                          bBuf + np * (16 * 64) + ((((uint32_t)(k16 * 2 + lnHi)) ^ ln3) << 4));
#pragma unroll
                for (int mf = 0; mf < 4; ++mf)
#pragma unroll
                    for (int nf = 0; nf < 4; ++nf) {
                        int np = nf >> 1, hi = nf & 1;
                        mma16816(acc[mf][nf], a[mf][0], a[mf][1], a[mf][2], a[mf][3],
                                 bq[np][hi], bq[np][hi + 2]);
                    }
            }
            __syncthreads();
        }
        int colb = nt * 128 + wn * 32;
        float* dstb = isenc ? g_A : g_Dp;
#pragma unroll
        for (int mf = 0; mf < 4; ++mf) {
            int m = mt * 128 + wm * 64 + mf * 16 + (lane >> 2);
#pragma unroll
            for (int nf = 0; nf < 4; ++nf) {
                int col = colb + nf * 8 + (lane & 3) * 2;
                float bx = 0.f, by = 0.f;
                if (isenc) { float2 bv = *(const float2*)(b1 + col); bx = bv.x; by = bv.y; }
                if (m < Mtot) {
                    float2 o = { acc[mf][nf][0] + bx, acc[mf][nf][1] + by };
                    *(float2*)(dstb + (size_t)m * 512 + col) = o;
                }
                if (m + 8 < Mtot) {
                    float2 o = { acc[mf][nf][2] + bx, acc[mf][nf][3] + by };
                    *(float2*)(dstb + (size_t)(m + 8) * 512 + col) = o;
                }
            }
        }
        __syncthreads();
    }
}

// ---------------- main kernel: out = tanh(encp+decp) @ W2^T + b2 ----------------
// 512 threads, 16 warps, warp grid 2(M)x8(N), warp tile 64x32.
// A smem: 128 rows x 512 halfs (1024B rows, XOR-8 chunk swizzle) = 128KB, built once
// B smem: 4-stage x 16KB, tile-linear (conflict-free ldsm at base+lane*16)
#define MT 512
#define MA_A 0
#define MA_B 131072
#define MA_SMEM (131072 + 4 * 16384)

__global__ __launch_bounds__(MT, 1) void main_kernel(const float* __restrict__ b2,
                                                     float* __restrict__ out) {
    extern __shared__ char sm[];
    uint32_t smb = smem_u32(sm);
    int tid = threadIdx.x, lane = tid & 31, wid = tid >> 5;
    int m0 = blockIdx.x * 128;
    const uint4* w2u = (const uint4*)g_w2;

    // kick off B prefetch for chunks 0..2 (overlaps with tanh prologue)
#pragma unroll
    for (int g = 0; g < 3; ++g) {
        const uint4* s = w2u + (size_t)g * 1024 + tid * 2;
        uint32_t d = smb + MA_B + g * 16384 + tid * 32;
        cp16(d, s); cp16(d + 16, s + 1);
        cp_commit();
    }

    // prologue: h = fp16(tanh(enc_proj + dec_proj)) into swizzled smem A
    {
        int r = tid >> 2, q = tid & 3;
        int m = m0 + r;
        const float4* pa = (const float4*)(g_A + (size_t)(m >> 6) * 512 + q * 128);
        int b = m / 25600, u = m & 63;
        const float4* pd = (const float4*)(g_Dp + (size_t)(b * 64 + u) * 512 + q * 128);
#pragma unroll 4
        for (int j = 0; j < 16; ++j) {
            float4 x0 = pa[2 * j], x1 = pa[2 * j + 1];
            float4 y0 = pd[2 * j], y1 = pd[2 * j + 1];
            uint4 qv;
            qv.x = pack_h2(fast_tanh(x0.x + y0.x), fast_tanh(x0.y + y0.y));
            qv.y = pack_h2(fast_tanh(x0.z + y0.z), fast_tanh(x0.w + y0.w));
            qv.z = pack_h2(fast_tanh(x1.x + y1.x), fast_tanh(x1.y + y1.y));
            qv.w = pack_h2(fast_tanh(x1.z + y1.z), fast_tanh(x1.w + y1.w));
            int cg = q * 16 + j;
            *(uint4*)(sm + MA_A + r * 1024 + ((cg ^ (r & 7)) << 4)) = qv;
        }
    }

    int wm = wid & 1, wn = wid >> 1;                 // 2 x 8 warps, warp tile 64x32
    uint32_t aBase = smb + MA_A + (wm * 64 + (lane & 15)) * 1024;
    uint32_t bLane = (uint32_t)(lane * 16);
    int ln7 = lane & 7, lnHi = lane >> 4;

    float acc[4][4][4];
#pragma unroll
    for (int i = 0; i < 4; ++i)
#pragma unroll
        for (int j = 0; j < 4; ++j)
#pragma unroll
            for (int q = 0; q < 4; ++q) acc[i][j][q] = 0.f;

    for (int ci = 0; ci < 64; ++ci) {
        cp_wait<2>();          // group ci complete (3 always pending before this)
        __syncthreads();       // data visible to all; all warps done with buf (ci+3)&3
        if (ci + 3 < 64) {     // prefetch chunk ci+3
            const uint4* s = w2u + (size_t)(ci + 3) * 1024 + tid * 2;
            uint32_t d = smb + MA_B + ((ci + 3) & 3) * 16384 + tid * 32;
            cp16(d, s); cp16(d + 16, s + 1);
        }
        cp_commit();           // always commit (empty group keeps pending count aligned)

        int kc = ci & 15;
        uint32_t bBuf = smb + MA_B + (ci & 3) * 16384;
#pragma unroll
        for (int k16 = 0; k16 < 2; ++k16) {
            uint32_t ach = (uint32_t)(kc * 4 + k16 * 2 + lnHi);
            uint32_t a[4][4];
#pragma unroll
            for (int mf = 0; mf < 4; ++mf)
                ldsm4(a[mf][0], a[mf][1], a[mf][2], a[mf][3],
                      aBase + mf * 16384 + ((ach ^ ln7) << 4));
            uint32_t bq[2][4];
#pragma unroll
            for (int np = 0; np < 2; ++np)
                ldsm4(bq[np][0], bq[np][1], bq[np][2], bq[np][3],
                      bBuf + (uint32_t)(((wn * 2 + np) * 2 + k16) * 512) + bLane);
#pragma unroll
            for (int mf = 0; mf < 4; ++mf)
#pragma unroll
                for (int nf = 0; nf < 4; ++nf) {
                    int np = nf >> 1, hi = nf & 1;
                    mma16816(acc[mf][nf], a[mf][0], a[mf][1], a[mf][2], a[mf][3],
                             bq[np][hi], bq[np][hi + 2]);
                }
        }

        if (kc == 15) {        // epilogue for nt = ci>>4: +b2, fp32 store, reset acc
            int nt = ci >> 4;
            int colb = nt * 256 + wn * 32;
#pragma unroll
            for (int mf = 0; mf < 4; ++mf) {
                int row = m0 + wm * 64 + mf * 16 + (lane >> 2);
#pragma unroll
                for (int nf = 0; nf < 4; ++nf) {
                    int col = colb + nf * 8 + (lane & 3) * 2;
                    float2 bv = *(const float2*)(b2 + col);
                    float2 o0 = { acc[mf][nf][0] + bv.x, acc[mf][nf][1] + bv.y };
                    float2 o1 = { acc[mf][nf][2] + bv.x, acc[mf][nf][3] + bv.y };
                    *(float2*)(out + (size_t)row * 1024 + col) = o0;
                    *(float2*)(out + (size_t)(row + 8) * 1024 + col) = o1;
                    acc[mf][nf][0] = acc[mf][nf][1] = acc[mf][nf][2] = acc[mf][nf][3] = 0.f;
                }
            }
        }
    }
}

// ---------------- launch ----------------
extern "C" void kernel_launch(void* const* d_in, const int* in_sizes, int n_in,
                              void* d_out, int out_size) {
    (void)in_sizes; (void)n_in; (void)out_size;
    const float* enc = (const float*)d_in[0];
    const float* dec = (const float*)d_in[1];
    const float* W1  = (const float*)d_in[2];
    const float* b1  = (const float*)d_in[3];
    const float* W2  = (const float*)d_in[4];
    const float* b2  = (const float*)d_in[5];
    float* out = (float*)d_out;

    cudaFuncSetAttribute(proj_kernel, cudaFuncAttributeMaxDynamicSharedMemorySize, PJ_SMEM);
    cudaFuncSetAttribute(main_kernel, cudaFuncAttributeMaxDynamicSharedMemorySize, MA_SMEM);

    prep_w1<<<160, NT>>>(W1);
    prep_w2<<<256, NT>>>(W2);
    proj_kernel<<<15, NT, PJ_SMEM>>>(enc, dec, b1);
    main_kernel<<<800, MT, MA_SMEM>>>(b2, out);
}